// round 1
// baseline (speedup 1.0000x reference)
#include <cuda_runtime.h>

// Problem constants (fixed by reference)
#define BWIN   2048
#define NTOK   49
#define CDIM   384
#define HHEADS 12
#define DH     32
#define NWMASK 64
#define THREEC 1152
#define MROWS  (BWIN * NTOK)   // 100352

// Scratch (allocation-free rule: __device__ globals)
__device__ float g_qkv[(size_t)MROWS * THREEC];   // [M, 1152]
__device__ float g_att[(size_t)MROWS * CDIM];     // [M, 384]

// ---------------------------------------------------------------------------
// SGEMM: C[m, n] = sum_k A[m,k] * W[n,k] + bias[n]
// A: [M, K] row-major, W: [Nout, K] row-major (i.e. C = A @ W^T + b)
// Tiles: BM=128, BN=128, BK=8. 256 threads, 8x8 outputs per thread.
// Requires M % 128 == 0, Nout % 128 == 0, K % 8 == 0 (all exact here).
// ---------------------------------------------------------------------------
__global__ __launch_bounds__(256) void sgemm_bias_kernel(
    const float* __restrict__ A,
    const float* __restrict__ W,
    const float* __restrict__ bias,
    float* __restrict__ C,
    int Nout, int K)
{
    __shared__ float As[8][128];
    __shared__ float Ws[8][128];

    const int tid = threadIdx.x;
    const int bm = blockIdx.y * 128;
    const int bn = blockIdx.x * 128;

    // global-load mapping: each thread loads one float4 of A and one of W
    const int lr = tid >> 1;            // tile row 0..127
    const int lc = (tid & 1) * 4;       // k sub-offset 0 or 4

    const float* Aptr = A + (size_t)(bm + lr) * K + lc;
    const float* Wptr = W + (size_t)(bn + lr) * K + lc;

    // compute mapping: 16x16 thread grid, 8x8 per thread
    const int ty = tid >> 4;
    const int tx = tid & 15;

    float acc[8][8];
#pragma unroll
    for (int i = 0; i < 8; i++)
#pragma unroll
        for (int j = 0; j < 8; j++) acc[i][j] = 0.0f;

    for (int k0 = 0; k0 < K; k0 += 8) {
        float4 av = *(const float4*)(Aptr + k0);
        float4 wv = *(const float4*)(Wptr + k0);
        __syncthreads();
        As[lc + 0][lr] = av.x; As[lc + 1][lr] = av.y;
        As[lc + 2][lr] = av.z; As[lc + 3][lr] = av.w;
        Ws[lc + 0][lr] = wv.x; Ws[lc + 1][lr] = wv.y;
        Ws[lc + 2][lr] = wv.z; Ws[lc + 3][lr] = wv.w;
        __syncthreads();

#pragma unroll
        for (int kk = 0; kk < 8; kk++) {
            float4 a0 = *(const float4*)&As[kk][ty * 8];
            float4 a1 = *(const float4*)&As[kk][ty * 8 + 4];
            float4 b0 = *(const float4*)&Ws[kk][tx * 8];
            float4 b1 = *(const float4*)&Ws[kk][tx * 8 + 4];
            float a[8] = {a0.x, a0.y, a0.z, a0.w, a1.x, a1.y, a1.z, a1.w};
            float b[8] = {b0.x, b0.y, b0.z, b0.w, b1.x, b1.y, b1.z, b1.w};
#pragma unroll
            for (int i = 0; i < 8; i++)
#pragma unroll
                for (int j = 0; j < 8; j++) acc[i][j] += a[i] * b[j];
        }
    }

    // epilogue: add bias, store
#pragma unroll
    for (int i = 0; i < 8; i++) {
        const int row = bm + ty * 8 + i;
        float* cp = C + (size_t)row * Nout + bn + tx * 8;
#pragma unroll
        for (int j = 0; j < 8; j += 4) {
            const float* bp = bias + bn + tx * 8 + j;
            float4 o;
            o.x = acc[i][j + 0] + bp[0];
            o.y = acc[i][j + 1] + bp[1];
            o.z = acc[i][j + 2] + bp[2];
            o.w = acc[i][j + 3] + bp[3];
            *(float4*)(cp + j) = o;
        }
    }
}

// ---------------------------------------------------------------------------
// Attention: one CTA per (window b, head h). q,k,v and scores in smem.
// g_qkv layout: [b*49+n][1152]; q at col h*32+d, k at +384, v at +768.
// mask window index = b % 64.  out -> g_att[b*49+n][h*32+d].
// ---------------------------------------------------------------------------
__global__ __launch_bounds__(128) void attn_kernel(const float* __restrict__ mask)
{
    const int b = blockIdx.x;   // 0..2047
    const int h = blockIdx.y;   // 0..11
    const int tid = threadIdx.x;

    __shared__ float qs[NTOK][DH];
    __shared__ float ks[NTOK][DH];
    __shared__ float vs[NTOK][DH];
    __shared__ float sc[NTOK][52];   // padded row to dodge conflicts

    const float scale = 0.17677669529663687f;  // 32^-0.5

    // load q (pre-scaled), k, v
    for (int idx = tid; idx < NTOK * DH; idx += 128) {
        const int n = idx >> 5;
        const int d = idx & 31;
        const float* base = g_qkv + (size_t)(b * NTOK + n) * THREEC + h * DH + d;
        qs[n][d] = base[0] * scale;
        ks[n][d] = base[CDIM];
        vs[n][d] = base[2 * CDIM];
    }
    __syncthreads();

    // scores + additive mask
    const float* mrow = mask + (size_t)(b & (NWMASK - 1)) * NTOK * NTOK;
    for (int idx = tid; idx < NTOK * NTOK; idx += 128) {
        const int i = idx / NTOK;
        const int j = idx - i * NTOK;
        float s = 0.0f;
#pragma unroll
        for (int d = 0; d < DH; d++) s += qs[i][d] * ks[j][d];
        sc[i][j] = s + mrow[idx];
    }
    __syncthreads();

    // row softmax (one thread per row; 49 < 128)
    if (tid < NTOK) {
        float m = -1e30f;
#pragma unroll 7
        for (int j = 0; j < NTOK; j++) m = fmaxf(m, sc[tid][j]);
        float sum = 0.0f;
#pragma unroll 7
        for (int j = 0; j < NTOK; j++) {
            float e = __expf(sc[tid][j] - m);
            sc[tid][j] = e;
            sum += e;
        }
        const float inv = 1.0f / sum;
#pragma unroll 7
        for (int j = 0; j < NTOK; j++) sc[tid][j] *= inv;
    }
    __syncthreads();

    // P @ V, scatter into [B,N,C] layout (heads merged back)
    for (int idx = tid; idx < NTOK * DH; idx += 128) {
        const int i = idx >> 5;
        const int d = idx & 31;
        float o = 0.0f;
#pragma unroll 7
        for (int j = 0; j < NTOK; j++) o += sc[i][j] * vs[j][d];
        g_att[(size_t)(b * NTOK + i) * CDIM + h * DH + d] = o;
    }
}

// ---------------------------------------------------------------------------
// launch
// ---------------------------------------------------------------------------
extern "C" void kernel_launch(void* const* d_in, const int* in_sizes, int n_in,
                              void* d_out, int out_size)
{
    const float* x      = (const float*)d_in[0];
    const float* mask   = (const float*)d_in[1];
    const float* qkv_w  = (const float*)d_in[2];
    const float* qkv_b  = (const float*)d_in[3];
    const float* proj_w = (const float*)d_in[4];
    const float* proj_b = (const float*)d_in[5];
    float* out = (float*)d_out;

    float* qkv_ptr;
    float* att_ptr;
    cudaGetSymbolAddress((void**)&qkv_ptr, g_qkv);
    cudaGetSymbolAddress((void**)&att_ptr, g_att);

    // 1) QKV GEMM: [100352,384] @ [384,1152]^T(+b)
    {
        dim3 grid(THREEC / 128, MROWS / 128);
        sgemm_bias_kernel<<<grid, 256>>>(x, qkv_w, qkv_b, qkv_ptr, THREEC, CDIM);
    }
    // 2) windowed attention
    {
        dim3 grid(BWIN, HHEADS);
        attn_kernel<<<grid, 128>>>(mask);
    }
    // 3) Proj GEMM: [100352,384] @ [384,384]^T(+b)
    {
        dim3 grid(CDIM / 128, MROWS / 128);
        sgemm_bias_kernel<<<grid, 256>>>(att_ptr, proj_w, proj_b, out, CDIM, CDIM);
    }
}

// round 2
// speedup vs baseline: 4.3510x; 4.3510x over previous
#include <cuda_runtime.h>
#include <cstdint>

// Problem constants (fixed by reference)
#define BWIN   2048
#define NTOK   49
#define CDIM   384
#define HHEADS 12
#define DH     32
#define NWMASK 64
#define THREEC 1152
#define MROWS  (BWIN * NTOK)   // 100352

// Scratch (allocation-free rule: __device__ globals)
__device__ float g_qkv[(size_t)MROWS * THREEC];   // [M, 1152]
__device__ float g_att[(size_t)MROWS * CDIM];     // [M, 384]

// ---------------------------------------------------------------------------
// tf32 helpers
// ---------------------------------------------------------------------------
__device__ __forceinline__ uint32_t f2tf32(float f) {
    uint32_t u;
    asm("cvt.rna.tf32.f32 %0, %1;" : "=r"(u) : "f"(f));
    return u;
}

__device__ __forceinline__ void mma_tf32(float c[4],
                                         uint32_t a0, uint32_t a1, uint32_t a2, uint32_t a3,
                                         uint32_t b0, uint32_t b1) {
    asm volatile(
        "mma.sync.aligned.m16n8k8.row.col.f32.tf32.tf32.f32 "
        "{%0,%1,%2,%3}, {%4,%5,%6,%7}, {%8,%9}, {%0,%1,%2,%3};"
        : "+f"(c[0]), "+f"(c[1]), "+f"(c[2]), "+f"(c[3])
        : "r"(a0), "r"(a1), "r"(a2), "r"(a3), "r"(b0), "r"(b1));
}

// ---------------------------------------------------------------------------
// tf32 tensor-core GEMM:  C[m,n] = sum_k A[m,k]*W[n,k] + bias[n]
// A: [M,K] row-major, W: [Nout,K] row-major.
// CTA tile 128x128, BK=16, 256 threads = 8 warps (2x4), warp tile 64x32.
// mma.m16n8k8: per warp 4 (m) x 4 (n) tiles per k8 step.
// Requires M%128==0, Nout%128==0, K%16==0 (exact here: K=384).
// ---------------------------------------------------------------------------
#define BK 16

__global__ __launch_bounds__(256, 2) void gemm_tf32_bias(
    const float* __restrict__ A,
    const float* __restrict__ W,
    const float* __restrict__ bias,
    float* __restrict__ C,
    int Nout, int K)
{
    __shared__ uint32_t As[2][BK][132];   // [k][m], padded
    __shared__ uint32_t Bs[2][BK][132];   // [k][n], padded
    __shared__ float bsm[128];

    const int tid  = threadIdx.x;
    const int bm   = blockIdx.y * 128;
    const int bn   = blockIdx.x * 128;
    const int lane = tid & 31;
    const int warp = tid >> 5;
    const int wm   = (warp >> 2) * 64;   // warp row offset (0,64)
    const int wn   = (warp & 3) * 32;    // warp col offset (0..96)
    const int t    = lane & 3;           // tid-in-group
    const int g    = lane >> 2;          // group id

    // global-load mapping: 256 threads x 2 float4 covers 128x16 tile
    const int ldr = tid >> 2;            // 0..63
    const int ldc = (tid & 3) << 2;      // 0,4,8,12

    if (tid < 128) bsm[tid] = bias[bn + tid];

    const float* Abase = A + (size_t)(bm + ldr) * K + ldc;
    const float* Wbase = W + (size_t)(bn + ldr) * K + ldc;

    float4 ar[2], wr[2];

    // prologue: load + store tile 0
    {
        ar[0] = *(const float4*)(Abase);
        ar[1] = *(const float4*)(Abase + (size_t)64 * K);
        wr[0] = *(const float4*)(Wbase);
        wr[1] = *(const float4*)(Wbase + (size_t)64 * K);
#pragma unroll
        for (int hh = 0; hh < 2; ++hh) {
            const int r = ldr + hh * 64;
            const float4 a = ar[hh], w = wr[hh];
            As[0][ldc + 0][r] = f2tf32(a.x);
            As[0][ldc + 1][r] = f2tf32(a.y);
            As[0][ldc + 2][r] = f2tf32(a.z);
            As[0][ldc + 3][r] = f2tf32(a.w);
            Bs[0][ldc + 0][r] = f2tf32(w.x);
            Bs[0][ldc + 1][r] = f2tf32(w.y);
            Bs[0][ldc + 2][r] = f2tf32(w.z);
            Bs[0][ldc + 3][r] = f2tf32(w.w);
        }
    }
    __syncthreads();

    float c[4][4][4] = {};

    const int NS = K / BK;   // 24
    int buf = 0;
    for (int s = 0; s < NS; ++s) {
        if (s + 1 < NS) {
            const int k0 = (s + 1) * BK;
            ar[0] = *(const float4*)(Abase + k0);
            ar[1] = *(const float4*)(Abase + (size_t)64 * K + k0);
            wr[0] = *(const float4*)(Wbase + k0);
            wr[1] = *(const float4*)(Wbase + (size_t)64 * K + k0);
        }

#pragma unroll
        for (int kk = 0; kk < BK; kk += 8) {
            uint32_t afr[4][4], bfr[4][2];
#pragma unroll
            for (int mi = 0; mi < 4; ++mi) {
                const int m0 = wm + mi * 16 + g;
                afr[mi][0] = As[buf][kk + t][m0];
                afr[mi][1] = As[buf][kk + t][m0 + 8];
                afr[mi][2] = As[buf][kk + t + 4][m0];
                afr[mi][3] = As[buf][kk + t + 4][m0 + 8];
            }
#pragma unroll
            for (int ni = 0; ni < 4; ++ni) {
                const int n0 = wn + ni * 8 + g;
                bfr[ni][0] = Bs[buf][kk + t][n0];
                bfr[ni][1] = Bs[buf][kk + t + 4][n0];
            }
#pragma unroll
            for (int mi = 0; mi < 4; ++mi)
#pragma unroll
                for (int ni = 0; ni < 4; ++ni)
                    mma_tf32(c[mi][ni],
                             afr[mi][0], afr[mi][1], afr[mi][2], afr[mi][3],
                             bfr[ni][0], bfr[ni][1]);
        }

        if (s + 1 < NS) {
            const int nb = buf ^ 1;
#pragma unroll
            for (int hh = 0; hh < 2; ++hh) {
                const int r = ldr + hh * 64;
                const float4 a = ar[hh], w = wr[hh];
                As[nb][ldc + 0][r] = f2tf32(a.x);
                As[nb][ldc + 1][r] = f2tf32(a.y);
                As[nb][ldc + 2][r] = f2tf32(a.z);
                As[nb][ldc + 3][r] = f2tf32(a.w);
                Bs[nb][ldc + 0][r] = f2tf32(w.x);
                Bs[nb][ldc + 1][r] = f2tf32(w.y);
                Bs[nb][ldc + 2][r] = f2tf32(w.z);
                Bs[nb][ldc + 3][r] = f2tf32(w.w);
            }
            __syncthreads();
            buf = nb;
        }
    }

    // epilogue: c-frag layout m16n8: c0 (g, 2t), c1 (g, 2t+1), c2 (g+8, 2t), c3 (g+8, 2t+1)
#pragma unroll
    for (int mi = 0; mi < 4; ++mi) {
#pragma unroll
        for (int ni = 0; ni < 4; ++ni) {
            const int row  = bm + wm + mi * 16 + g;
            const int colL = wn + ni * 8 + 2 * t;
            const int col  = bn + colL;
            const float b0v = bsm[colL], b1v = bsm[colL + 1];
            float2 v0 = make_float2(c[mi][ni][0] + b0v, c[mi][ni][1] + b1v);
            float2 v1 = make_float2(c[mi][ni][2] + b0v, c[mi][ni][3] + b1v);
            *(float2*)(C + (size_t)row * Nout + col)       = v0;
            *(float2*)(C + (size_t)(row + 8) * Nout + col) = v1;
        }
    }
}

// ---------------------------------------------------------------------------
// Attention: one CTA (64 threads) per (window b, head h).
// Register-blocked: scores phase keeps one K column per thread in 32 regs
// (q rows broadcast via LDS.128); PV phase maps lanes to head-dims.
// ---------------------------------------------------------------------------
__global__ __launch_bounds__(64) void attn_kernel(const float* __restrict__ mask)
{
    const int b = blockIdx.x;   // 0..2047
    const int h = blockIdx.y;   // 0..11
    const int tid = threadIdx.x;

    __shared__ __align__(16) float qs[NTOK][DH];
    __shared__ __align__(16) float ks[NTOK][DH];
    __shared__ __align__(16) float vs[NTOK][DH];
    __shared__ float sc[NTOK][53];   // 53: odd-ish stride -> conflict-free softmax rows

    const float scale = 0.17677669529663687f;  // 32^-0.5

    // load q (pre-scaled), k, v
    for (int idx = tid; idx < NTOK * DH; idx += 64) {
        const int n = idx >> 5;
        const int d = idx & 31;
        const float* base = g_qkv + (size_t)(b * NTOK + n) * THREEC + h * DH + d;
        qs[n][d] = base[0] * scale;
        ks[n][d] = base[CDIM];
        vs[n][d] = base[2 * CDIM];
    }
    __syncthreads();

    // scores: thread j owns key column j in registers
    if (tid < NTOK) {
        float4 kv[8];
#pragma unroll
        for (int dd = 0; dd < 8; ++dd) kv[dd] = ((const float4*)ks[tid])[dd];
        const float* mcol = mask + (size_t)(b & (NWMASK - 1)) * NTOK * NTOK + tid;
#pragma unroll 7
        for (int i = 0; i < NTOK; ++i) {
            const float4* q4 = (const float4*)qs[i];
            float s = 0.0f;
#pragma unroll
            for (int dd = 0; dd < 8; ++dd) {
                const float4 q = q4[dd];
                s += q.x * kv[dd].x + q.y * kv[dd].y + q.z * kv[dd].z + q.w * kv[dd].w;
            }
            sc[i][tid] = s + mcol[i * NTOK];
        }
    }
    __syncthreads();

    // row softmax
    if (tid < NTOK) {
        float m = -1e30f;
#pragma unroll 7
        for (int j = 0; j < NTOK; j++) m = fmaxf(m, sc[tid][j]);
        float sum = 0.0f;
#pragma unroll 7
        for (int j = 0; j < NTOK; j++) {
            const float e = __expf(sc[tid][j] - m);
            sc[tid][j] = e;
            sum += e;
        }
        const float inv = 1.0f / sum;
#pragma unroll 7
        for (int j = 0; j < NTOK; j++) sc[tid][j] *= inv;
    }
    __syncthreads();

    // P @ V: lane d per warp, rows interleaved across the 2 warps
    const int d  = tid & 31;
    const int i0 = tid >> 5;
    for (int i = i0; i < NTOK; i += 2) {
        float o = 0.0f;
#pragma unroll 7
        for (int j = 0; j < NTOK; j++) o += sc[i][j] * vs[j][d];
        g_att[(size_t)(b * NTOK + i) * CDIM + h * DH + d] = o;
    }
}

// ---------------------------------------------------------------------------
// launch
// ---------------------------------------------------------------------------
extern "C" void kernel_launch(void* const* d_in, const int* in_sizes, int n_in,
                              void* d_out, int out_size)
{
    const float* x      = (const float*)d_in[0];
    const float* mask   = (const float*)d_in[1];
    const float* qkv_w  = (const float*)d_in[2];
    const float* qkv_b  = (const float*)d_in[3];
    const float* proj_w = (const float*)d_in[4];
    const float* proj_b = (const float*)d_in[5];
    float* out = (float*)d_out;

    float* qkv_ptr;
    float* att_ptr;
    cudaGetSymbolAddress((void**)&qkv_ptr, g_qkv);
    cudaGetSymbolAddress((void**)&att_ptr, g_att);

    // 1) QKV GEMM: [100352,384] @ [384,1152]^T (+b)
    {
        dim3 grid(THREEC / 128, MROWS / 128);
        gemm_tf32_bias<<<grid, 256>>>(x, qkv_w, qkv_b, qkv_ptr, THREEC, CDIM);
    }
    // 2) windowed attention
    {
        dim3 grid(BWIN, HHEADS);
        attn_kernel<<<grid, 64>>>(mask);
    }
    // 3) Proj GEMM: [100352,384] @ [384,384]^T (+b)
    {
        dim3 grid(CDIM / 128, MROWS / 128);
        gemm_tf32_bias<<<grid, 256>>>(att_ptr, proj_w, proj_b, out, CDIM, CDIM);
    }
}

// round 3
// speedup vs baseline: 5.2115x; 1.1978x over previous
#include <cuda_runtime.h>
#include <cstdint>

// Problem constants (fixed by reference)
#define BWIN   2048
#define NTOK   49
#define CDIM   384
#define HHEADS 12
#define DH     32
#define NWMASK 64
#define THREEC 1152
#define MROWS  (BWIN * NTOK)   // 100352

// Scratch (allocation-free rule: __device__ globals)
__device__ float g_qkv[(size_t)MROWS * THREEC];   // [M, 1152]
__device__ float g_att[(size_t)MROWS * CDIM];     // [M, 384]

// ---------------------------------------------------------------------------
// tf32 helpers
// ---------------------------------------------------------------------------
__device__ __forceinline__ uint32_t f2tf32(float f) {
    uint32_t u;
    asm("cvt.rna.tf32.f32 %0, %1;" : "=r"(u) : "f"(f));
    return u;
}

__device__ __forceinline__ void mma_tf32(float c[4],
                                         uint32_t a0, uint32_t a1, uint32_t a2, uint32_t a3,
                                         uint32_t b0, uint32_t b1) {
    asm volatile(
        "mma.sync.aligned.m16n8k8.row.col.f32.tf32.tf32.f32 "
        "{%0,%1,%2,%3}, {%4,%5,%6,%7}, {%8,%9}, {%0,%1,%2,%3};"
        : "+f"(c[0]), "+f"(c[1]), "+f"(c[2]), "+f"(c[3])
        : "r"(a0), "r"(a1), "r"(a2), "r"(a3), "r"(b0), "r"(b1));
}

// ---------------------------------------------------------------------------
// tf32 tensor-core GEMM v2:  C[m,n] = sum_k A[m,k]*W[n,k] + bias[n]
// CTA tile 256x128, BK=16, 256 threads = 8 warps (4m x 2n), warp tile 64x64.
// Smem holds MMA fragments directly (fragment-permuted layout):
//   A word idx: ((k8*16 + mi)*4 + reg)*32 + lane     (mi = 16-row group 0..15)
//   B word idx: ((k8*16 + ni)*2 + kh )*32 + lane     (ni =  8-col group 0..15)
// Consumer: coalesced conflict-free LDS.32. Producer: conflict-free STS.128.
// Requires M%256==0, Nout%128==0, K%16==0 (exact: 100352, {1152,384}, 384).
// ---------------------------------------------------------------------------
__global__ __launch_bounds__(256, 1) void gemm_tf32_v2(
    const float* __restrict__ A,
    const float* __restrict__ W,
    const float* __restrict__ bias,
    float* __restrict__ C,
    int Nout, int K)
{
    __shared__ __align__(16) uint32_t As[2][4096];  // 16KB x2
    __shared__ __align__(16) uint32_t Bs[2][2048];  //  8KB x2

    const int tid  = threadIdx.x;
    const int bm   = blockIdx.y * 256;
    const int bn   = blockIdx.x * 128;
    const int lane = tid & 31;
    const int warp = tid >> 5;
    const int warp_m = warp >> 1;    // 0..3  (64-row slab)
    const int warp_n = warp & 1;     // 0..1  (64-col slab)
    const int g = lane >> 2;
    const int t = lane & 3;

    // global-load mapping: A 256x16 -> 4 float4/thread, B 128x16 -> 2 float4/thread
    const int ldr = tid >> 2;            // 0..63
    const int ldc = (tid & 3) << 2;      // 0,4,8,12
    const int k8s = ldc >> 3;            // 0,0,1,1
    const int khs = (ldc >> 2) & 1;      // 0,1,0,1

    const float* Ab = A + (size_t)(bm + ldr) * K + ldc;
    const float* Wb = W + (size_t)(bn + ldr) * K + ldc;

    // producer store offsets (word units)
    int aoff[4], boff[2];
#pragma unroll
    for (int i = 0; i < 4; ++i) {
        const int r  = ldr + i * 64;
        const int mi = r >> 4;
        const int g2 = r & 7;
        const int hi = (r >> 3) & 1;
        aoff[i] = ((k8s * 16 + mi) * 4 + (khs * 2 + hi)) * 32 + g2 * 4;
    }
#pragma unroll
    for (int i = 0; i < 2; ++i) {
        const int cL = ldr + i * 64;
        const int ni = cL >> 3;
        const int g2 = cL & 7;
        boff[i] = ((k8s * 16 + ni) * 2 + khs) * 32 + g2 * 4;
    }

    float4 ar[4], wr[2];

    auto load_g = [&](int k0) {
        ar[0] = *(const float4*)(Ab + k0);
        ar[1] = *(const float4*)(Ab + (size_t)64  * K + k0);
        ar[2] = *(const float4*)(Ab + (size_t)128 * K + k0);
        ar[3] = *(const float4*)(Ab + (size_t)192 * K + k0);
        wr[0] = *(const float4*)(Wb + k0);
        wr[1] = *(const float4*)(Wb + (size_t)64  * K + k0);
    };
    auto stash = [&](int bf) {
#pragma unroll
        for (int i = 0; i < 4; ++i) {
            uint4 v;
            v.x = f2tf32(ar[i].x); v.y = f2tf32(ar[i].y);
            v.z = f2tf32(ar[i].z); v.w = f2tf32(ar[i].w);
            *(uint4*)&As[bf][aoff[i]] = v;
        }
#pragma unroll
        for (int i = 0; i < 2; ++i) {
            uint4 v;
            v.x = f2tf32(wr[i].x); v.y = f2tf32(wr[i].y);
            v.z = f2tf32(wr[i].z); v.w = f2tf32(wr[i].w);
            *(uint4*)&Bs[bf][boff[i]] = v;
        }
    };

    // prologue
    load_g(0);
    stash(0);
    __syncthreads();

    float acc[4][8][4] = {};

    const int NS = K / 16;   // 24
    int buf = 0;
    for (int s = 0; s < NS; ++s) {
        if (s + 1 < NS) load_g((s + 1) * 16);

#pragma unroll
        for (int k8 = 0; k8 < 2; ++k8) {
            uint32_t af[4][4], bfr[8][2];
            const uint32_t* Ap = &As[buf][((k8 * 16 + warp_m * 4) * 4) * 32 + lane];
            const uint32_t* Bp = &Bs[buf][((k8 * 16 + warp_n * 8) * 2) * 32 + lane];
#pragma unroll
            for (int mi = 0; mi < 4; ++mi)
#pragma unroll
                for (int r = 0; r < 4; ++r)
                    af[mi][r] = Ap[(mi * 4 + r) * 32];
#pragma unroll
            for (int ni = 0; ni < 8; ++ni) {
                bfr[ni][0] = Bp[ni * 64];
                bfr[ni][1] = Bp[ni * 64 + 32];
            }
#pragma unroll
            for (int mi = 0; mi < 4; ++mi)
#pragma unroll
                for (int ni = 0; ni < 8; ++ni)
                    mma_tf32(acc[mi][ni],
                             af[mi][0], af[mi][1], af[mi][2], af[mi][3],
                             bfr[ni][0], bfr[ni][1]);
        }

        if (s + 1 < NS) {
            stash(buf ^ 1);
            __syncthreads();
            buf ^= 1;
        }
    }

    // epilogue: frag layout m16n8: c0=(g,2t) c1=(g,2t+1) c2=(g+8,2t) c3=(g+8,2t+1)
#pragma unroll
    for (int mi = 0; mi < 4; ++mi) {
#pragma unroll
        for (int ni = 0; ni < 8; ++ni) {
            const int row = bm + warp_m * 64 + mi * 16 + g;
            const int col = bn + warp_n * 64 + ni * 8 + 2 * t;
            const float b0v = __ldg(bias + col);
            const float b1v = __ldg(bias + col + 1);
            float2 v0 = make_float2(acc[mi][ni][0] + b0v, acc[mi][ni][1] + b1v);
            float2 v1 = make_float2(acc[mi][ni][2] + b0v, acc[mi][ni][3] + b1v);
            *(float2*)(C + (size_t)row * Nout + col)       = v0;
            *(float2*)(C + (size_t)(row + 8) * Nout + col) = v1;
        }
    }
}

// ---------------------------------------------------------------------------
// Attention: one CTA (128 threads) per (window b, head h).
// Scores: i-range split across warp pairs, K column cached in registers,
//         conflict-free k reads (ks padded to 36).
// PV: 4-row register blocking, vs[j][d] shared across 4 FMAs.
// ---------------------------------------------------------------------------
__global__ __launch_bounds__(128) void attn_kernel(const float* __restrict__ mask)
{
    const int b = blockIdx.x;   // 0..2047
    const int h = blockIdx.y;   // 0..11
    const int tid = threadIdx.x;

    __shared__ __align__(16) float qs[NTOK][DH];
    __shared__ __align__(16) float ks[NTOK][36];   // pad 36 -> 4-way max on row loads
    __shared__ __align__(16) float vs[NTOK][DH];
    __shared__ float sc[NTOK][53];                 // 53: conflict-free column access

    const float scale = 0.17677669529663687f;  // 32^-0.5

    // load q (pre-scaled), k, v  (coalesced: 32 consecutive floats per row)
    for (int idx = tid; idx < NTOK * DH; idx += 128) {
        const int n = idx >> 5;
        const int d = idx & 31;
        const float* base = g_qkv + (size_t)(b * NTOK + n) * THREEC + h * DH + d;
        qs[n][d] = base[0] * scale;
        ks[n][d] = base[CDIM];
        vs[n][d] = base[2 * CDIM];
    }
    __syncthreads();

    // scores: thread (half, j) owns key column j; warps 0-1 do i<25, warps 2-3 do i>=25
    {
        const int half = tid >> 6;
        const int j = tid & 63;
        if (j < NTOK) {
            float4 kv[8];
#pragma unroll
            for (int dd = 0; dd < 8; ++dd) kv[dd] = *(const float4*)&ks[j][dd * 4];
            const float* mcol = mask + (size_t)(b & (NWMASK - 1)) * NTOK * NTOK + j;
            const int i0 = half ? 25 : 0;
            const int i1 = half ? NTOK : 25;
            for (int i = i0; i < i1; ++i) {
                const float4* q4 = (const float4*)qs[i];
                float s = 0.0f;
#pragma unroll
                for (int dd = 0; dd < 8; ++dd) {
                    const float4 q = q4[dd];
                    s += q.x * kv[dd].x + q.y * kv[dd].y + q.z * kv[dd].z + q.w * kv[dd].w;
                }
                sc[i][j] = s + mcol[i * NTOK];
            }
        }
    }
    __syncthreads();

    // row softmax
    if (tid < NTOK) {
        float m = -1e30f;
#pragma unroll 7
        for (int j = 0; j < NTOK; j++) m = fmaxf(m, sc[tid][j]);
        float sum = 0.0f;
#pragma unroll 7
        for (int j = 0; j < NTOK; j++) {
            const float e = __expf(sc[tid][j] - m);
            sc[tid][j] = e;
            sum += e;
        }
        const float inv = 1.0f / sum;
#pragma unroll 7
        for (int j = 0; j < NTOK; j++) sc[tid][j] *= inv;
    }
    __syncthreads();

    // P @ V: lane d, warp handles 4-row blocks
    const int d = tid & 31;
    const int w = tid >> 5;
    for (int i0 = w * 4; i0 < NTOK; i0 += 16) {
        const int nrows = (NTOK - i0 < 4) ? (NTOK - i0) : 4;
        float o0 = 0.f, o1 = 0.f, o2 = 0.f, o3 = 0.f;
        for (int j = 0; j < NTOK; ++j) {
            const float vj = vs[j][d];
            o0 += sc[i0][j] * vj;
            if (nrows > 1) o1 += sc[i0 + 1][j] * vj;
            if (nrows > 2) o2 += sc[i0 + 2][j] * vj;
            if (nrows > 3) o3 += sc[i0 + 3][j] * vj;
        }
        float* op = g_att + (size_t)(b * NTOK + i0) * CDIM + h * DH + d;
        op[0] = o0;
        if (nrows > 1) op[CDIM]     = o1;
        if (nrows > 2) op[2 * CDIM] = o2;
        if (nrows > 3) op[3 * CDIM] = o3;
    }
}

// ---------------------------------------------------------------------------
// launch
// ---------------------------------------------------------------------------
extern "C" void kernel_launch(void* const* d_in, const int* in_sizes, int n_in,
                              void* d_out, int out_size)
{
    const float* x      = (const float*)d_in[0];
    const float* mask   = (const float*)d_in[1];
    const float* qkv_w  = (const float*)d_in[2];
    const float* qkv_b  = (const float*)d_in[3];
    const float* proj_w = (const float*)d_in[4];
    const float* proj_b = (const float*)d_in[5];
    float* out = (float*)d_out;

    float* qkv_ptr;
    float* att_ptr;
    cudaGetSymbolAddress((void**)&qkv_ptr, g_qkv);
    cudaGetSymbolAddress((void**)&att_ptr, g_att);

    // 1) QKV GEMM: [100352,384] @ [384,1152]^T (+b)
    {
        dim3 grid(THREEC / 128, MROWS / 256);
        gemm_tf32_v2<<<grid, 256>>>(x, qkv_w, qkv_b, qkv_ptr, THREEC, CDIM);
    }
    // 2) windowed attention
    {
        dim3 grid(BWIN, HHEADS);
        attn_kernel<<<grid, 128>>>(mask);
    }
    // 3) Proj GEMM: [100352,384] @ [384,384]^T (+b)
    {
        dim3 grid(CDIM / 128, MROWS / 256);
        gemm_tf32_v2<<<grid, 256>>>(att_ptr, proj_w, proj_b, out, CDIM, CDIM);
    }
}